// round 1
// baseline (speedup 1.0000x reference)
#include <cuda_runtime.h>
#include <cuda_bf16.h>
#include <math.h>

// Problem constants
#define BB 32
#define SS 1024
#define DIN 128
#define HH 256
#define G4H 1024          // 4*H
#define MROWS 32768       // B*S
#define GC 64             // CTAs per direction in recurrence
#define NHU 4             // hidden units per CTA (H/GC)

// ---------------- scratch (static device allocations; no cudaMalloc) -------
__device__ float g_xp_f[SS * BB * G4H];   // 134 MB  [t][b][4H]
__device__ float g_xp_b[SS * BB * G4H];   // 134 MB
__device__ float g_h0[BB * SS * 512];     // 67 MB   [b][t][512]
__device__ float g_h1[BB * SS * 512];     // 67 MB
__device__ float g_ctx[BB * SS * 512];    // 67 MB
__device__ float g_hstate[2 * 2 * HH * BB]; // [dir][buf][k][b]
__device__ int   g_ctr[2];

// ---------------- init: zero counters + h state ----------------------------
__global__ void init_kernel() {
    int tid = threadIdx.x + blockIdx.x * blockDim.x;
    if (tid < 2) g_ctr[tid] = 0;
    for (int i = tid; i < 2 * 2 * HH * BB; i += blockDim.x * gridDim.x)
        g_hstate[i] = 0.f;
}

// ---------------- GEMM: out[r][n] = sum_k A[r][k] * W[n][k] + bias[n] ------
// mode 0: row r -> (t = r>>5, b = r&31), A row at b*sB + t*sT  (for xp: out r = t*B+b)
// mode 1: A row at r*K (plain row-major)
__global__ void __launch_bounds__(256) gemm_kernel(
    const float* __restrict__ Aext, int asel,
    const float* __restrict__ W, const float* __restrict__ bias,
    float* __restrict__ outext, int osel,
    int N, int K, long sB, long sT, int mode)
{
    const float* A = (asel == 0) ? Aext : (asel == 1 ? g_h0 : g_ctx);
    float* out = (osel == 2) ? outext : (osel == 0 ? g_xp_f : g_xp_b);

    __shared__ float As[8][128];
    __shared__ float Ws[8][128];

    int tid = threadIdx.x;
    int row0 = blockIdx.x * 128;
    int col0 = blockIdx.y * 128;

    int lrw = tid >> 1;          // 0..127 : which row of tile this thread loads
    int lk  = (tid & 1) * 4;     // 0 or 4 : which 4 k's

    long aoff;
    {
        int R = row0 + lrw;
        if (mode == 0) { int b = R & 31; int t = R >> 5; aoff = (long)b * sB + (long)t * sT; }
        else           { aoff = (long)R * K; }
    }
    const float* Ap = A + aoff + lk;
    const float* Wp = W + (long)(col0 + lrw) * K + lk;

    int tx = tid & 15, ty = tid >> 4;

    float acc[8][8];
#pragma unroll
    for (int i = 0; i < 8; i++)
#pragma unroll
        for (int j = 0; j < 8; j++) acc[i][j] = 0.f;

    for (int k0 = 0; k0 < K; k0 += 8) {
        float4 av = *(const float4*)(Ap + k0);
        float4 wv = *(const float4*)(Wp + k0);
        As[lk + 0][lrw] = av.x; As[lk + 1][lrw] = av.y;
        As[lk + 2][lrw] = av.z; As[lk + 3][lrw] = av.w;
        Ws[lk + 0][lrw] = wv.x; Ws[lk + 1][lrw] = wv.y;
        Ws[lk + 2][lrw] = wv.z; Ws[lk + 3][lrw] = wv.w;
        __syncthreads();
#pragma unroll
        for (int kk = 0; kk < 8; kk++) {
            float4 a0 = *(const float4*)&As[kk][ty * 4];
            float4 a1 = *(const float4*)&As[kk][ty * 4 + 64];
            float4 b0 = *(const float4*)&Ws[kk][tx * 4];
            float4 b1 = *(const float4*)&Ws[kk][tx * 4 + 64];
            float ar[8] = {a0.x, a0.y, a0.z, a0.w, a1.x, a1.y, a1.z, a1.w};
            float br[8] = {b0.x, b0.y, b0.z, b0.w, b1.x, b1.y, b1.z, b1.w};
#pragma unroll
            for (int i = 0; i < 8; i++)
#pragma unroll
                for (int j = 0; j < 8; j++)
                    acc[i][j] = fmaf(ar[i], br[j], acc[i][j]);
        }
        __syncthreads();
    }

#pragma unroll
    for (int i = 0; i < 8; i++) {
        int r = row0 + ty * 4 + (i & 3) + (i >> 2) * 64;
        float* orow = out + (long)r * N + col0;
#pragma unroll
        for (int j = 0; j < 8; j++) {
            int cc = tx * 4 + (j & 3) + (j >> 2) * 64;
            orow[cc] = acc[i][j] + bias[col0 + cc];
        }
    }
}

// ---------------- recurrence: both directions of one layer ------------------
// grid = 2*GC blocks, 256 threads. blockIdx < GC => forward, else backward.
// Each CTA owns NHU hidden units => 4*NHU = 16 gate rows of W_hh in SMEM.
// Per step: all CTAs of a direction read full h (global, L2), compute their
// gate slice, update c/h, publish h to the other buffer, barrier via atomic ctr.
__global__ void __launch_bounds__(256) rec_kernel(
    const float* __restrict__ w_hh_f, const float* __restrict__ w_hh_b, int layer)
{
    extern __shared__ float sm[];
    float* W_sh = sm;                 // [16][256]
    float* h_sh = sm + 16 * 256;      // [256][32]  (k-major, b fastest)
    float* g_sh = h_sh + 256 * 32;    // [16][32]

    int tid  = threadIdx.x;
    int dir  = blockIdx.x / GC;
    int cid  = blockIdx.x % GC;
    int j0   = cid * NHU;
    const float* Whh = dir ? w_hh_b : w_hh_f;
    const float* xp  = dir ? g_xp_b : g_xp_f;
    float* hout = layer ? g_h1 : g_h0;

    // load this CTA's 16 gate rows of W_hh (row lr = q*NHU + jl -> global q*H + j0 + jl)
    for (int idx = tid; idx < 16 * 256; idx += 256) {
        int lr = idx >> 8, k = idx & 255;
        int q = lr >> 2, jl = lr & 3;
        W_sh[idx] = Whh[(q * HH + j0 + jl) * HH + k];
    }

    int lane = tid & 31, warp = tid >> 5;
    int lr0 = warp * 2, lr1 = warp * 2 + 1;
    int gr0 = (lr0 >> 2) * HH + j0 + (lr0 & 3);
    int gr1 = (lr1 >> 2) * HH + j0 + (lr1 & 3);

    float c = 0.f;  // cell state, held by tid<128: (jl = tid>>5, b = tid&31)

    volatile int* ctr = (volatile int*)&g_ctr[dir];
    float* hsbase = g_hstate + dir * 2 * (HH * BB);

    __syncthreads();

    for (int t = 0; t < SS; t++) {
        int tt = dir ? (SS - 1 - t) : t;
        const float* hsg = hsbase + (t & 1) * (HH * BB);

        // prefetch xp preactivations for this thread's two gate rows (batch=lane)
        long xbase = (long)tt * (BB * G4H) + (long)lane * G4H;
        float xv0 = xp[xbase + gr0];
        float xv1 = xp[xbase + gr1];

        // load full h for this direction (written by peer SMs -> bypass L1)
        for (int idx = tid; idx < HH * BB; idx += 256)
            h_sh[idx] = __ldcg(&hsg[idx]);
        __syncthreads();

        // dot products: acc[lr] over k of W[lr][k]*h[k][lane]
        float acc0 = 0.f, acc1 = 0.f;
        const float* w0 = W_sh + lr0 * 256;
        const float* w1 = W_sh + lr1 * 256;
        const float* hc = h_sh + lane;
#pragma unroll 4
        for (int k = 0; k < 256; k += 4) {
            float4 w0v = *(const float4*)(w0 + k);
            float4 w1v = *(const float4*)(w1 + k);
            float h0 = hc[(k + 0) * 32];
            float h1 = hc[(k + 1) * 32];
            float h2 = hc[(k + 2) * 32];
            float h3 = hc[(k + 3) * 32];
            acc0 = fmaf(w0v.x, h0, acc0); acc1 = fmaf(w1v.x, h0, acc1);
            acc0 = fmaf(w0v.y, h1, acc0); acc1 = fmaf(w1v.y, h1, acc1);
            acc0 = fmaf(w0v.z, h2, acc0); acc1 = fmaf(w1v.z, h2, acc1);
            acc0 = fmaf(w0v.w, h3, acc0); acc1 = fmaf(w1v.w, h3, acc1);
        }
        g_sh[lr0 * 32 + lane] = acc0 + xv0;
        g_sh[lr1 * 32 + lane] = acc1 + xv1;
        __syncthreads();

        if (tid < 128) {
            int jl = tid >> 5, b = tid & 31;
            float gi = g_sh[(0 * 4 + jl) * 32 + b];
            float gf = g_sh[(1 * 4 + jl) * 32 + b];
            float gg = g_sh[(2 * 4 + jl) * 32 + b];
            float go = g_sh[(3 * 4 + jl) * 32 + b];
            float si = 1.f / (1.f + expf(-gi));
            float sf = 1.f / (1.f + expf(-gf));
            float so = 1.f / (1.f + expf(-go));
            float tg = tanhf(gg);
            c = sf * c + si * tg;
            float hval = so * tanhf(c);
            // publish h for next step (double buffer), and to layer output
            float* hsn = hsbase + ((t + 1) & 1) * (HH * BB);
            hsn[(j0 + jl) * 32 + b] = hval;
            hout[((long)b * SS + tt) * 512 + dir * HH + j0 + jl] = hval;
            __threadfence();
        }
        __syncthreads();

        if (t < SS - 1) {
            if (tid == 0) {
                atomicAdd(&g_ctr[dir], 1);
                int target = GC * (t + 1);
                while (*ctr < target) { }
            }
            __syncthreads();
            __threadfence();
        }
    }
}

// ---------------- attention: causal softmax-weighted running average -------
// One CTA per batch b, 512 threads.
__global__ void __launch_bounds__(512) attn_kernel(
    const float* __restrict__ attn_w, const float* __restrict__ attn_b)
{
    __shared__ float aw[512];
    __shared__ float e_sh[SS];
    __shared__ float red[16];

    int b = blockIdx.x, tid = threadIdx.x;
    int lane = tid & 31, warp = tid >> 5;
    const float* hb = g_h1 + (long)b * SS * 512;

    aw[tid] = attn_w[tid];
    float sb = attn_b[0];
    __syncthreads();

    // s[t] = h[b,t,:].attn_w + attn_b   (warp per t)
    for (int t = warp; t < SS; t += 16) {
        const float* hp = hb + (long)t * 512;
        float s = 0.f;
#pragma unroll
        for (int i = lane; i < 512; i += 32) s = fmaf(hp[i], aw[i], s);
#pragma unroll
        for (int o = 16; o; o >>= 1) s += __shfl_xor_sync(0xffffffffu, s, o);
        if (lane == 0) e_sh[t] = s + sb;
    }
    __syncthreads();

    // max over t
    float m = -3.4e38f;
    for (int t = tid; t < SS; t += 512) m = fmaxf(m, e_sh[t]);
#pragma unroll
    for (int o = 16; o; o >>= 1) m = fmaxf(m, __shfl_xor_sync(0xffffffffu, m, o));
    if (lane == 0) red[warp] = m;
    __syncthreads();
    m = red[0];
#pragma unroll
    for (int i = 1; i < 16; i++) m = fmaxf(m, red[i]);

    for (int t = tid; t < SS; t += 512) e_sh[t] = expf(e_sh[t] - m);
    __syncthreads();

    // causal cumsum per hidden dim d = tid (exactly 512 dims)
    int d = tid;
    float num = 0.f, den = 0.f;
    const float* hd = hb + d;
    float* cd = g_ctx + (long)b * SS * 512 + d;
    for (int t = 0; t < SS; t++) {
        float ev = e_sh[t];
        den += ev;
        num = fmaf(ev, hd[(long)t * 512], num);
        cd[(long)t * 512] = num / den;
    }
}

// ---------------- launch ----------------------------------------------------
extern "C" void kernel_launch(void* const* d_in, const int* in_sizes, int n_in,
                              void* d_out, int out_size)
{
    const float* x       = (const float*)d_in[0];
    const float* wih0f   = (const float*)d_in[1];
    const float* whh0f   = (const float*)d_in[2];
    const float* b0f     = (const float*)d_in[3];
    const float* wih0b   = (const float*)d_in[4];
    const float* whh0b   = (const float*)d_in[5];
    const float* b0b     = (const float*)d_in[6];
    const float* wih1f   = (const float*)d_in[7];
    const float* whh1f   = (const float*)d_in[8];
    const float* b1f     = (const float*)d_in[9];
    const float* wih1b   = (const float*)d_in[10];
    const float* whh1b   = (const float*)d_in[11];
    const float* b1b     = (const float*)d_in[12];
    const float* attn_w  = (const float*)d_in[13];
    const float* attn_b  = (const float*)d_in[14];
    const float* head_w  = (const float*)d_in[15];
    const float* head_b  = (const float*)d_in[16];
    float* out = (float*)d_out;

    const int REC_SMEM = (16 * 256 + 256 * 32 + 16 * 32) * sizeof(float); // 51200 B
    cudaFuncSetAttribute(rec_kernel, cudaFuncAttributeMaxDynamicSharedMemorySize, REC_SMEM);

    // ---- layer 0 ----
    init_kernel<<<32, 256>>>();
    gemm_kernel<<<dim3(MROWS / 128, G4H / 128), 256>>>(x, 0, wih0f, b0f, nullptr, 0,
                                                       G4H, DIN, (long)SS * DIN, DIN, 0);
    gemm_kernel<<<dim3(MROWS / 128, G4H / 128), 256>>>(x, 0, wih0b, b0b, nullptr, 1,
                                                       G4H, DIN, (long)SS * DIN, DIN, 0);
    rec_kernel<<<2 * GC, 256, REC_SMEM>>>(whh0f, whh0b, 0);

    // ---- layer 1 ----
    init_kernel<<<32, 256>>>();
    gemm_kernel<<<dim3(MROWS / 128, G4H / 128), 256>>>(nullptr, 1, wih1f, b1f, nullptr, 0,
                                                       G4H, 512, (long)SS * 512, 512, 0);
    gemm_kernel<<<dim3(MROWS / 128, G4H / 128), 256>>>(nullptr, 1, wih1b, b1b, nullptr, 1,
                                                       G4H, 512, (long)SS * 512, 512, 0);
    rec_kernel<<<2 * GC, 256, REC_SMEM>>>(whh1f, whh1b, 1);

    // ---- attention + head ----
    attn_kernel<<<BB, 512>>>(attn_w, attn_b);
    gemm_kernel<<<dim3(MROWS / 128, 1), 256>>>(nullptr, 2, head_w, head_b, out, 2,
                                               DIN, 512, 0, 0, 1);
}

// round 7
// speedup vs baseline: 1.0164x; 1.0164x over previous
#include <cuda_runtime.h>
#include <cuda_bf16.h>
#include <math.h>
#include <stdint.h>

// Problem constants
#define BB 32
#define SS 1024
#define DIN 128
#define HH 256
#define G4H 1024          // 4*H
#define MROWS 32768       // B*S
#define GC 64             // CTAs per direction in recurrence
#define NHU 4             // hidden units per CTA (H/GC)

// ---------------- scratch (static device allocations; no cudaMalloc) -------
__device__ float g_xp_f[SS * BB * G4H];   // 134 MB  [t][b][4H]
__device__ float g_xp_b[SS * BB * G4H];   // 134 MB
__device__ float g_h0[BB * SS * 512];     // 67 MB   [b][t][512]
__device__ float g_h1[BB * SS * 512];     // 67 MB
__device__ float g_ctx[BB * SS * 512];    // 67 MB
__device__ float g_hstate[2 * 2 * HH * BB]; // [dir][buf][k][b]
__device__ int   g_ctr[2];

// ---------------- init: zero counters + h state ----------------------------
__global__ void init_kernel() {
    int tid = threadIdx.x + blockIdx.x * blockDim.x;
    if (tid < 2) g_ctr[tid] = 0;
    for (int i = tid; i < 2 * 2 * HH * BB; i += blockDim.x * gridDim.x)
        g_hstate[i] = 0.f;
}

// ---------------- tf32 tensor-core GEMM ------------------------------------
// out[r][n] = sum_k A[r][k] * W[n][k] + bias[n]
// mode 0: tile row R -> A row at (R&31)*sB + (R>>5)*sT  (xp layout)
// mode 1: A row at R*K
// Block tile 128x128, BK=32, 8 warps (4x2), warp tile 32x64, m16n8k8 tf32.
#define BK 32
#define KSTRIDE 136   // smem row stride (k-major): bank = (8k + r) % 32, conflict-free

__device__ __forceinline__ void mma_tf32(float* c, const uint32_t* a, const uint32_t* b) {
    asm volatile(
        "mma.sync.aligned.m16n8k8.row.col.f32.tf32.tf32.f32 "
        "{%0,%1,%2,%3}, {%4,%5,%6,%7}, {%8,%9}, {%0,%1,%2,%3};"
        : "+f"(c[0]), "+f"(c[1]), "+f"(c[2]), "+f"(c[3])
        : "r"(a[0]), "r"(a[1]), "r"(a[2]), "r"(a[3]), "r"(b[0]), "r"(b[1]));
}

__global__ void __launch_bounds__(256, 2) gemm_kernel(
    const float* __restrict__ Aext, int asel,
    const float* __restrict__ W, const float* __restrict__ bias,
    float* __restrict__ outext, int osel,
    int N, int K, long sB, long sT, int mode)
{
    const float* A = (asel == 0) ? Aext : (asel == 1 ? g_h0 : g_ctx);
    float* out = (osel == 2) ? outext : (osel == 0 ? g_xp_f : g_xp_b);

    __shared__ float As[BK][KSTRIDE];   // k-major: As[k][r]
    __shared__ float Bs[BK][KSTRIDE];   // k-major: Bs[k][n]

    int tid  = threadIdx.x;
    int row0 = blockIdx.x * 128;
    int col0 = blockIdx.y * 128;

    // global-load mapping: lr = tile row/col (0..127), lh = k sub-offset (0 or 16)
    int lr = tid & 127;
    int lh = (tid >> 7) * 16;

    long aoff;
    if (mode == 0) { int R = row0 + lr; aoff = (long)(R & 31) * sB + (long)(R >> 5) * sT; }
    else           { aoff = (long)(row0 + lr) * K; }
    const float* Ap = A + aoff + lh;
    const float* Wp = W + (long)(col0 + lr) * K + lh;

    int lane = tid & 31, warp = tid >> 5;
    int wm = warp >> 1, wn = warp & 1;       // warp tile: rows wm*32, cols wn*64
    int gid = lane >> 2, tid4 = lane & 3;

    float acc[2][8][4];
#pragma unroll
    for (int mi = 0; mi < 2; mi++)
#pragma unroll
        for (int ni = 0; ni < 8; ni++)
#pragma unroll
            for (int q = 0; q < 4; q++) acc[mi][ni][q] = 0.f;

    for (int k0 = 0; k0 < K; k0 += BK) {
#pragma unroll
        for (int c = 0; c < 4; c++) {
            float4 av = *(const float4*)(Ap + k0 + c * 4);
            float4 wv = *(const float4*)(Wp + k0 + c * 4);
            int kk = lh + c * 4;
            As[kk + 0][lr] = av.x; As[kk + 1][lr] = av.y;
            As[kk + 2][lr] = av.z; As[kk + 3][lr] = av.w;
            Bs[kk + 0][lr] = wv.x; Bs[kk + 1][lr] = wv.y;
            Bs[kk + 2][lr] = wv.z; Bs[kk + 3][lr] = wv.w;
        }
        __syncthreads();

#pragma unroll
        for (int kk = 0; kk < BK; kk += 8) {
            uint32_t af[2][4];
#pragma unroll
            for (int mi = 0; mi < 2; mi++) {
                int r0 = wm * 32 + mi * 16 + gid;
                af[mi][0] = __float_as_uint(As[kk + tid4][r0]);
                af[mi][1] = __float_as_uint(As[kk + tid4][r0 + 8]);
                af[mi][2] = __float_as_uint(As[kk + tid4 + 4][r0]);
                af[mi][3] = __float_as_uint(As[kk + tid4 + 4][r0 + 8]);
            }
            uint32_t bf[8][2];
#pragma unroll
            for (int ni = 0; ni < 8; ni++) {
                int n0 = wn * 64 + ni * 8 + gid;
                bf[ni][0] = __float_as_uint(Bs[kk + tid4][n0]);
                bf[ni][1] = __float_as_uint(Bs[kk + tid4 + 4][n0]);
            }
#pragma unroll
            for (int mi = 0; mi < 2; mi++)
#pragma unroll
                for (int ni = 0; ni < 8; ni++)
                    mma_tf32(acc[mi][ni], af[mi], bf[ni]);
        }
        __syncthreads();
    }

    // epilogue: D rows gid / gid+8, cols 2*tid4(+1) per 8-col group, + bias
#pragma unroll
    for (int mi = 0; mi < 2; mi++) {
        int r = row0 + wm * 32 + mi * 16 + gid;
#pragma unroll
        for (int ni = 0; ni < 8; ni++) {
            int cc = col0 + wn * 64 + ni * 8 + tid4 * 2;
            float b0 = bias[cc], b1 = bias[cc + 1];
            float2 v0 = make_float2(acc[mi][ni][0] + b0, acc[mi][ni][1] + b1);
            float2 v1 = make_float2(acc[mi][ni][2] + b0, acc[mi][ni][3] + b1);
            *(float2*)(out + (long)r * N + cc)       = v0;
            *(float2*)(out + (long)(r + 8) * N + cc) = v1;
        }
    }
}

// ---------------- recurrence (VERBATIM from the R1 kernel that passed) ------
// grid = 2*GC blocks, 256 threads. blockIdx < GC => forward, else backward.
__global__ void __launch_bounds__(256) rec_kernel(
    const float* __restrict__ w_hh_f, const float* __restrict__ w_hh_b, int layer)
{
    extern __shared__ float sm[];
    float* W_sh = sm;                 // [16][256]
    float* h_sh = sm + 16 * 256;      // [256][32]  (k-major, b fastest)
    float* g_sh = h_sh + 256 * 32;    // [16][32]

    int tid  = threadIdx.x;
    int dir  = blockIdx.x / GC;
    int cid  = blockIdx.x % GC;
    int j0   = cid * NHU;
    const float* Whh = dir ? w_hh_b : w_hh_f;
    const float* xp  = dir ? g_xp_b : g_xp_f;
    float* hout = layer ? g_h1 : g_h0;

    // load this CTA's 16 gate rows of W_hh
    for (int idx = tid; idx < 16 * 256; idx += 256) {
        int lr = idx >> 8, k = idx & 255;
        int q = lr >> 2, jl = lr & 3;
        W_sh[idx] = Whh[(q * HH + j0 + jl) * HH + k];
    }

    int lane = tid & 31, warp = tid >> 5;
    int lr0 = warp * 2, lr1 = warp * 2 + 1;
    int gr0 = (lr0 >> 2) * HH + j0 + (lr0 & 3);
    int gr1 = (lr1 >> 2) * HH + j0 + (lr1 & 3);

    float c = 0.f;  // cell state, held by tid<128: (jl = tid>>5, b = tid&31)

    volatile int* ctr = (volatile int*)&g_ctr[dir];
    float* hsbase = g_hstate + dir * 2 * (HH * BB);

    __syncthreads();

    for (int t = 0; t < SS; t++) {
        int tt = dir ? (SS - 1 - t) : t;
        const float* hsg = hsbase + (t & 1) * (HH * BB);

        long xbase = (long)tt * (BB * G4H) + (long)lane * G4H;
        float xv0 = xp[xbase + gr0];
        float xv1 = xp[xbase + gr1];

        // load full h for this direction (written by peer SMs -> bypass L1)
        for (int idx = tid; idx < HH * BB; idx += 256)
            h_sh[idx] = __ldcg(&hsg[idx]);
        __syncthreads();

        // dot products: acc[lr] over k of W[lr][k]*h[k][lane]
        float acc0 = 0.f, acc1 = 0.f;
        const float* w0 = W_sh + lr0 * 256;
        const float* w1 = W_sh + lr1 * 256;
        const float* hc = h_sh + lane;
#pragma unroll 4
        for (int k = 0; k < 256; k += 4) {
            float4 w0v = *(const float4*)(w0 + k);
            float4 w1v = *(const float4*)(w1 + k);
            float h0 = hc[(k + 0) * 32];
            float h1 = hc[(k + 1) * 32];
            float h2 = hc[(k + 2) * 32];
            float h3 = hc[(k + 3) * 32];
            acc0 = fmaf(w0v.x, h0, acc0); acc1 = fmaf(w1v.x, h0, acc1);
            acc0 = fmaf(w0v.y, h1, acc0); acc1 = fmaf(w1v.y, h1, acc1);
            acc0 = fmaf(w0v.z, h2, acc0); acc1 = fmaf(w1v.z, h2, acc1);
            acc0 = fmaf(w0v.w, h3, acc0); acc1 = fmaf(w1v.w, h3, acc1);
        }
        g_sh[lr0 * 32 + lane] = acc0 + xv0;
        g_sh[lr1 * 32 + lane] = acc1 + xv1;
        __syncthreads();

        if (tid < 128) {
            int jl = tid >> 5, b = tid & 31;
            float gi = g_sh[(0 * 4 + jl) * 32 + b];
            float gf = g_sh[(1 * 4 + jl) * 32 + b];
            float gg = g_sh[(2 * 4 + jl) * 32 + b];
            float go = g_sh[(3 * 4 + jl) * 32 + b];
            float si = 1.f / (1.f + expf(-gi));
            float sf = 1.f / (1.f + expf(-gf));
            float so = 1.f / (1.f + expf(-go));
            float tg = tanhf(gg);
            c = sf * c + si * tg;
            float hval = so * tanhf(c);
            float* hsn = hsbase + ((t + 1) & 1) * (HH * BB);
            hsn[(j0 + jl) * 32 + b] = hval;
            hout[((long)b * SS + tt) * 512 + dir * HH + j0 + jl] = hval;
            __threadfence();
        }
        __syncthreads();

        if (t < SS - 1) {
            if (tid == 0) {
                atomicAdd(&g_ctr[dir], 1);
                int target = GC * (t + 1);
                while (*ctr < target) { }
            }
            __syncthreads();
            __threadfence();
        }
    }
}

// ---------------- attention: causal softmax-weighted running average -------
__global__ void __launch_bounds__(512) attn_kernel(
    const float* __restrict__ attn_w, const float* __restrict__ attn_b)
{
    __shared__ float aw[512];
    __shared__ float e_sh[SS];
    __shared__ float red[16];

    int b = blockIdx.x, tid = threadIdx.x;
    int lane = tid & 31, warp = tid >> 5;
    const float* hb = g_h1 + (long)b * SS * 512;

    aw[tid] = attn_w[tid];
    float sb = attn_b[0];
    __syncthreads();

    for (int t = warp; t < SS; t += 16) {
        const float* hp = hb + (long)t * 512;
        float s = 0.f;
#pragma unroll
        for (int i = lane; i < 512; i += 32) s = fmaf(hp[i], aw[i], s);
#pragma unroll
        for (int o = 16; o; o >>= 1) s += __shfl_xor_sync(0xffffffffu, s, o);
        if (lane == 0) e_sh[t] = s + sb;
    }
    __syncthreads();

    float m = -3.4e38f;
    for (int t = tid; t < SS; t += 512) m = fmaxf(m, e_sh[t]);
#pragma unroll
    for (int o = 16; o; o >>= 1) m = fmaxf(m, __shfl_xor_sync(0xffffffffu, m, o));
    if (lane == 0) red[warp] = m;
    __syncthreads();
    m = red[0];
#pragma unroll
    for (int i = 1; i < 16; i++) m = fmaxf(m, red[i]);

    for (int t = tid; t < SS; t += 512) e_sh[t] = expf(e_sh[t] - m);
    __syncthreads();

    int d = tid;
    float num = 0.f, den = 0.f;
    const float* hd = hb + d;
    float* cd = g_ctx + (long)b * SS * 512 + d;
    for (int t = 0; t < SS; t++) {
        float ev = e_sh[t];
        den += ev;
        num = fmaf(ev, hd[(long)t * 512], num);
        cd[(long)t * 512] = num / den;
    }
}

// ---------------- launch ----------------------------------------------------
extern "C" void kernel_launch(void* const* d_in, const int* in_sizes, int n_in,
                              void* d_out, int out_size)
{
    const float* x       = (const float*)d_in[0];
    const float* wih0f   = (const float*)d_in[1];
    const float* whh0f   = (const float*)d_in[2];
    const float* b0f     = (const float*)d_in[3];
    const float* wih0b   = (const float*)d_in[4];
    const float* whh0b   = (const float*)d_in[5];
    const float* b0b     = (const float*)d_in[6];
    const float* wih1f   = (const float*)d_in[7];
    const float* whh1f   = (const float*)d_in[8];
    const float* b1f     = (const float*)d_in[9];
    const float* wih1b   = (const float*)d_in[10];
    const float* whh1b   = (const float*)d_in[11];
    const float* b1b     = (const float*)d_in[12];
    const float* attn_w  = (const float*)d_in[13];
    const float* attn_b  = (const float*)d_in[14];
    const float* head_w  = (const float*)d_in[15];
    const float* head_b  = (const float*)d_in[16];
    float* out = (float*)d_out;

    const int REC_SMEM = (16 * 256 + 256 * 32 + 16 * 32) * sizeof(float); // 51200 B
    cudaFuncSetAttribute(rec_kernel, cudaFuncAttributeMaxDynamicSharedMemorySize, REC_SMEM);

    // ---- layer 0 ----
    init_kernel<<<32, 256>>>();
    gemm_kernel<<<dim3(MROWS / 128, G4H / 128), 256>>>(x, 0, wih0f, b0f, nullptr, 0,
                                                       G4H, DIN, (long)SS * DIN, DIN, 0);
    gemm_kernel<<<dim3(MROWS / 128, G4H / 128), 256>>>(x, 0, wih0b, b0b, nullptr, 1,
                                                       G4H, DIN, (long)SS * DIN, DIN, 0);
    rec_kernel<<<2 * GC, 256, REC_SMEM>>>(whh0f, whh0b, 0);

    // ---- layer 1 ----
    init_kernel<<<32, 256>>>();
    gemm_kernel<<<dim3(MROWS / 128, G4H / 128), 256>>>(nullptr, 1, wih1f, b1f, nullptr, 0,
                                                       G4H, 512, (long)SS * 512, 512, 0);
    gemm_kernel<<<dim3(MROWS / 128, G4H / 128), 256>>>(nullptr, 1, wih1b, b1b, nullptr, 1,
                                                       G4H, 512, (long)SS * 512, 512, 0);
    rec_kernel<<<2 * GC, 256, REC_SMEM>>>(whh1f, whh1b, 1);

    // ---- attention + head ----
    attn_kernel<<<BB, 512>>>(attn_w, attn_b);
    gemm_kernel<<<dim3(MROWS / 128, 1), 256>>>(nullptr, 2, head_w, head_b, out, 2,
                                               DIN, 512, 0, 0, 1);
}